// round 13
// baseline (speedup 1.0000x reference)
#include <cuda_runtime.h>

#define H 51
#define BB 16
#define NTHREADS 352
#define KHALF 26
#define HOFF 424          // 26*16+8 floats -> 1696B ≡ 32 (mod 128)
#define HSTRIDE 864       // 3456B ≡ 0 (mod 128): parity keeps bank phase
#define HT2 (2*HSTRIDE + 16)  // hT2 float offset; byte 6976 ≡ 64 (mod 128)
#define GROWS 459
#define GPU 9             // gbuf pitch in ull/float2 units
#define GPF 18
#define REDS 208          // 13 rows x 16

typedef unsigned long long ull;

#define FFMA2(d, a, b_) asm("fma.rn.f32x2 %0, %1, %2, %0;" : "+l"(d) : "l"(a), "l"(b_))
#define ADDF2(d, a)     asm("add.rn.f32x2 %0, %0, %1;"     : "+l"(d) : "l"(a))

__device__ __forceinline__ ull pack2(float lo, float hi) {
    ull r;
    asm("mov.b64 %0, {%1,%2};" : "=l"(r) : "f"(lo), "f"(hi));
    return r;
}
__device__ __forceinline__ float2 unpack2(ull v) {
    float lo, hi;
    asm("mov.b64 {%0,%1}, %2;" : "=f"(lo), "=f"(hi) : "l"(v));
    return make_float2(lo, hi);
}
__device__ __forceinline__ float sigf(float v) {
    return __fdividef(1.0f, 1.0f + __expf(-v));
}
__device__ __forceinline__ float tanh_f(float v) {
    return 1.0f - __fdividef(2.0f, __expf(2.0f * v) + 1.0f);
}
__device__ __forceinline__ int hidx(int k) { return k * 16 + (k >= KHALF ? 8 : 0); }

__global__ __launch_bounds__(NTHREADS, 1)
void gru2_kernel(const float* __restrict__ input,
                 const float* __restrict__ w_ih1, const float* __restrict__ w_hh1,
                 const float* __restrict__ b_ih1, const float* __restrict__ b_hh1,
                 const float* __restrict__ w_ih2, const float* __restrict__ w_hh2,
                 const float* __restrict__ b_ih2, const float* __restrict__ b_hh2,
                 const float* __restrict__ w_lin, const float* __restrict__ b_lin,
                 float* __restrict__ out, int T, int F)
{
    extern __shared__ float sm[];
    float* hT1   = sm;                        // [2][864]
    float* hT2p  = sm + HT2;                  // [2][864]
    ull*   gbufU = (ull*)(sm + HT2 + 2 * HSTRIDE);   // [459][9], float 3472
    float* gbufF = (float*)gbufU;
    const float2* g2 = (const float2*)gbufF;
    float* tabs  = (float*)(gbufU + GROWS * GPU);    // 7*51 + 1 pad
    float* xbuf  = tabs + 7 * H + 1;          // [16]
    float* oacc  = xbuf + BB;                 // [2][16]
    float* red   = oacc + 2 * BB;             // [2][13][16]

    const int tid  = threadIdx.x;
    const int lane = tid & 31;
    const int wrp  = tid >> 5;
    const int gb0  = blockIdx.x * BB;
    const int TOT  = T + F;

    for (int j = tid; j < HT2 + 2 * HSTRIDE; j += NTHREADS) sm[j] = 0.f;
    if (tid < H) {
        tabs[tid]         = __ldg(&w_ih1[tid]);
        tabs[H + tid]     = __ldg(&w_ih1[H + tid]);
        tabs[2 * H + tid] = __ldg(&w_ih1[2 * H + tid]);
        tabs[3 * H + tid] = __ldg(&b_ih1[tid]);
        tabs[4 * H + tid] = __ldg(&b_ih1[H + tid]);
        tabs[5 * H + tid] = __ldg(&b_ih1[2 * H + tid]);
        tabs[6 * H + tid] = __ldg(&w_lin[tid]);
    }

    // ---- dot threads: gate-triples, k-split ----
    const bool comp = (tid < 306);
    const int p    = tid >> 1;                // triple id 0..152
    const int half = tid & 1;
    const unsigned pmask = 0x3u << (tid & 30);
    const int region = comp ? p / 51 : 0;     // 0: whh1·h1, 1: whh2·h2, 2: wih2·h1
    const int u      = comp ? (p - region * 51) : 0;
    const float* base = (region == 0) ? w_hh1 : ((region == 1) ? w_hh2 : w_ih2);
    const float* bsrc = (region == 0) ? b_hh1 : ((region == 1) ? b_hh2 : b_ih2);
    const int hsel = (region == 1);

    float wA[KHALF], wB[KHALF], wC[KHALF];
    #pragma unroll
    for (int j = 0; j < KHALF; ++j) {
        int k = half * KHALF + j;
        bool v = comp && (k < H);
        wA[j] = v ? __ldg(&base[u * H + k]) : 0.f;
        wB[j] = v ? __ldg(&base[(H + u) * H + k]) : 0.f;
        wC[j] = v ? __ldg(&base[(2 * H + u) * H + k]) : 0.f;
    }
    float bA = comp ? __ldg(&bsrc[u]) : 0.f;
    float bB = comp ? __ldg(&bsrc[H + u]) : 0.f;
    float bC = comp ? __ldg(&bsrc[2 * H + u]) : 0.f;
    const ull biasA = half ? 0ULL : pack2(bA, bA);
    const ull biasB = half ? 0ULL : pack2(bB, bB);
    const ull biasC = half ? 0ULL : pack2(bC, bC);
    const float blin = __ldg(&b_lin[0]);
    const int pxor = hsel ? 0 : 1;
    const float* hbase = hsel ? hT2p : hT1;
    const int hoff = half * HOFF;
    const int growA = region * 153 + u;

    __syncthreads();

    for (int i = 0; i <= TOT; ++i) {
        const int par = i & 1;

        // ================= DOT STAGE (3 rows/thread) + helper warp 10 =================
        if (comp) {
            const float* hp = hbase + (par ^ pxor) * HSTRIDE + hoff;
            ull aA[8], aB[8], aC[8];
            #pragma unroll
            for (int bp = 0; bp < 8; ++bp) { aA[bp] = biasA; aB[bp] = biasB; aC[bp] = biasC; }
            #pragma unroll
            for (int k = 0; k < KHALF; ++k) {
                const ulonglong2* qq = (const ulonglong2*)(hp + k * 16);
                ulonglong2 q0 = qq[0], q1 = qq[1], q2 = qq[2], q3 = qq[3];
                ull wd;
                wd = pack2(wA[k], wA[k]);
                FFMA2(aA[0], wd, q0.x); FFMA2(aA[1], wd, q0.y);
                FFMA2(aA[2], wd, q1.x); FFMA2(aA[3], wd, q1.y);
                FFMA2(aA[4], wd, q2.x); FFMA2(aA[5], wd, q2.y);
                FFMA2(aA[6], wd, q3.x); FFMA2(aA[7], wd, q3.y);
                wd = pack2(wB[k], wB[k]);
                FFMA2(aB[0], wd, q0.x); FFMA2(aB[1], wd, q0.y);
                FFMA2(aB[2], wd, q1.x); FFMA2(aB[3], wd, q1.y);
                FFMA2(aB[4], wd, q2.x); FFMA2(aB[5], wd, q2.y);
                FFMA2(aB[6], wd, q3.x); FFMA2(aB[7], wd, q3.y);
                wd = pack2(wC[k], wC[k]);
                FFMA2(aC[0], wd, q0.x); FFMA2(aC[1], wd, q0.y);
                FFMA2(aC[2], wd, q1.x); FFMA2(aC[3], wd, q1.y);
                FFMA2(aC[4], wd, q2.x); FFMA2(aC[5], wd, q2.y);
                FFMA2(aC[6], wd, q3.x); FFMA2(aC[7], wd, q3.y);
            }
            #pragma unroll
            for (int bp = 0; bp < 8; ++bp) {
                ull t;
                t = __shfl_xor_sync(pmask, aA[bp], 1); ADDF2(aA[bp], t);
                t = __shfl_xor_sync(pmask, aB[bp], 1); ADDF2(aB[bp], t);
                t = __shfl_xor_sync(pmask, aC[bp], 1); ADDF2(aC[bp], t);
            }
            if (!half) {
                ull* gA = gbufU + growA * GPU;
                ull* gB = gbufU + (growA + 51) * GPU;
                ull* gC = gbufU + (growA + 102) * GPU;
                #pragma unroll
                for (int bp = 0; bp < 8; ++bp) { gA[bp] = aA[bp]; gB[bp] = aB[bp]; gC[bp] = aC[bp]; }
            }
        } else if (tid >= 320) {
            int l = tid - 320;
            if (i >= 2 && i <= T) {              // finalize o[i-2] from red scratch
                int b = l & 15, hf = l >> 4;
                const float* rr = red + (par ^ 1) * REDS;
                float s = 0.f;
                #pragma unroll
                for (int r = 0; r < 7; ++r) {
                    int row = hf * 7 + r;
                    if (row < 13) s += rr[row * 16 + b];
                }
                s += __shfl_xor_sync(0xFFFFFFFFu, s, 16);
                if (hf == 0) out[(size_t)(gb0 + b) * TOT + (i - 2)] = s + blin;
            }
            if (l < 16) {
                red[par * REDS + 12 * 16 + l] = 0.f;
                if (i >= T) oacc[par * 16 + l] = 0.f;
                if (i < T)  xbuf[l] = __ldg(&input[(size_t)(gb0 + l) * T + i]);
            }
        }
        __syncthreads();

        // ================= POINTWISE STAGE =================
        float* h2c = hT2p + par * HSTRIDE;          // h2[i-2]
        float* h2n = hT2p + (par ^ 1) * HSTRIDE;    // h2[i-1]
        float* h1c = hT1 + (par ^ 1) * HSTRIDE;     // h1[i-1]
        float* h1n = hT1 + par * HSTRIDE;           // h1[i]

        if (i < T) {
            // ---- L2 pointwise + warp reduction (pass 0: tasks 0..351 on all warps) ----
            {
                float v0 = 0.f, v1 = 0.f;
                if (i > 0) {
                    int uu = tid >> 3, bp = tid & 7;
                    int hx = hidx(uu) + 2 * bp;
                    float2 dir = g2[(306 + uu) * GPU + bp];
                    float2 diz = g2[(357 + uu) * GPU + bp];
                    float2 din = g2[(408 + uu) * GPU + bp];
                    float2 d2r = g2[(153 + uu) * GPU + bp];
                    float2 d2z = g2[(204 + uu) * GPU + bp];
                    float2 d2n = g2[(255 + uu) * GPU + bp];
                    float2 hold = *(const float2*)(h2c + hx);
                    float r0 = sigf(dir.x + d2r.x), r1 = sigf(dir.y + d2r.y);
                    float z0 = sigf(diz.x + d2z.x), z1 = sigf(diz.y + d2z.y);
                    float n0 = tanh_f(fmaf(r0, d2n.x, din.x));
                    float n1 = tanh_f(fmaf(r1, d2n.y, din.y));
                    float h0 = n0 + z0 * (hold.x - n0);
                    float h1 = n1 + z1 * (hold.y - n1);
                    *(float2*)(h2n + hx) = make_float2(h0, h1);
                    float wl = tabs[6 * H + uu];
                    v0 = wl * h0; v1 = wl * h1;
                }
                ull pv = pack2(v0, v1), t;
                t = __shfl_xor_sync(0xFFFFFFFFu, pv, 8);  ADDF2(pv, t);
                t = __shfl_xor_sync(0xFFFFFFFFu, pv, 16); ADDF2(pv, t);
                if ((lane & 24) == 0)
                    *(float2*)(red + par * REDS + wrp * 16 + 2 * (lane & 7)) = unpack2(pv);
            }
            // ---- pass 1: tasks 352..407 ----
            if (tid < 32) {                       // u 44..47, full warp 0 -> red row 11
                float v0 = 0.f, v1 = 0.f;
                if (i > 0) {
                    int j = tid + 352;
                    int uu = j >> 3, bp = j & 7;
                    int hx = hidx(uu) + 2 * bp;
                    float2 dir = g2[(306 + uu) * GPU + bp];
                    float2 diz = g2[(357 + uu) * GPU + bp];
                    float2 din = g2[(408 + uu) * GPU + bp];
                    float2 d2r = g2[(153 + uu) * GPU + bp];
                    float2 d2z = g2[(204 + uu) * GPU + bp];
                    float2 d2n = g2[(255 + uu) * GPU + bp];
                    float2 hold = *(const float2*)(h2c + hx);
                    float r0 = sigf(dir.x + d2r.x), r1 = sigf(dir.y + d2r.y);
                    float z0 = sigf(diz.x + d2z.x), z1 = sigf(diz.y + d2z.y);
                    float n0 = tanh_f(fmaf(r0, d2n.x, din.x));
                    float n1 = tanh_f(fmaf(r1, d2n.y, din.y));
                    float h0 = n0 + z0 * (hold.x - n0);
                    float h1 = n1 + z1 * (hold.y - n1);
                    *(float2*)(h2n + hx) = make_float2(h0, h1);
                    float wl = tabs[6 * H + uu];
                    v0 = wl * h0; v1 = wl * h1;
                }
                ull pv = pack2(v0, v1), t;
                t = __shfl_xor_sync(0xFFFFFFFFu, pv, 8);  ADDF2(pv, t);
                t = __shfl_xor_sync(0xFFFFFFFFu, pv, 16); ADDF2(pv, t);
                if ((lane & 24) == 0)
                    *(float2*)(red + par * REDS + 11 * 16 + 2 * (lane & 7)) = unpack2(pv);
            } else if (tid < 56 && i > 0) {       // u 48..50 (24 tasks) -> atomics, red row 12
                int j = tid + 352;
                int uu = j >> 3, bp = j & 7;
                int hx = hidx(uu) + 2 * bp;
                float2 dir = g2[(306 + uu) * GPU + bp];
                float2 diz = g2[(357 + uu) * GPU + bp];
                float2 din = g2[(408 + uu) * GPU + bp];
                float2 d2r = g2[(153 + uu) * GPU + bp];
                float2 d2z = g2[(204 + uu) * GPU + bp];
                float2 d2n = g2[(255 + uu) * GPU + bp];
                float2 hold = *(const float2*)(h2c + hx);
                float r0 = sigf(dir.x + d2r.x), r1 = sigf(dir.y + d2r.y);
                float z0 = sigf(diz.x + d2z.x), z1 = sigf(diz.y + d2z.y);
                float n0 = tanh_f(fmaf(r0, d2n.x, din.x));
                float n1 = tanh_f(fmaf(r1, d2n.y, din.y));
                float h0 = n0 + z0 * (hold.x - n0);
                float h1 = n1 + z1 * (hold.y - n1);
                *(float2*)(h2n + hx) = make_float2(h0, h1);
                float wl = tabs[6 * H + uu];
                float* rr = red + par * REDS + 12 * 16;
                atomicAdd(&rr[2 * bp],     wl * h0);
                atomicAdd(&rr[2 * bp + 1], wl * h1);
            }
            // ---- L1 pointwise (408 tasks over 352 threads) ----
            for (int j = tid; j < 408; j += NTHREADS) {
                int uu = j >> 3, bp = j & 7;
                int hx = hidx(uu) + 2 * bp;
                float2 x2 = *(const float2*)(xbuf + 2 * bp);
                float2 ar = g2[uu * GPU + bp];
                float2 az = g2[(51 + uu) * GPU + bp];
                float2 an = g2[(102 + uu) * GPU + bp];
                float2 hold = *(const float2*)(h1c + hx);
                float w1r = tabs[uu], w1z = tabs[H + uu], w1n = tabs[2 * H + uu];
                float c1r = tabs[3 * H + uu], c1z = tabs[4 * H + uu], c1n = tabs[5 * H + uu];
                float r0 = sigf(fmaf(x2.x, w1r, c1r) + ar.x);
                float r1 = sigf(fmaf(x2.y, w1r, c1r) + ar.y);
                float z0 = sigf(fmaf(x2.x, w1z, c1z) + az.x);
                float z1 = sigf(fmaf(x2.y, w1z, c1z) + az.y);
                float n0 = tanh_f(fmaf(x2.x, w1n, c1n) + r0 * an.x);
                float n1 = tanh_f(fmaf(x2.y, w1n, c1n) + r1 * an.y);
                float h0 = n0 + z0 * (hold.x - n0);
                float h1 = n1 + z1 * (hold.y - n1);
                *(float2*)(h1n + hx) = make_float2(h0, h1);
            }
            __syncthreads();
        } else {
            // ---- future mode: L2 (+atomic o) -> sync -> out + L1 -> sync ----
            float* oa = oacc + par * 16;
            for (int j = tid; j < 408; j += NTHREADS) {
                int uu = j >> 3, bp = j & 7;
                int hx = hidx(uu) + 2 * bp;
                float2 dir = g2[(306 + uu) * GPU + bp];
                float2 diz = g2[(357 + uu) * GPU + bp];
                float2 din = g2[(408 + uu) * GPU + bp];
                float2 d2r = g2[(153 + uu) * GPU + bp];
                float2 d2z = g2[(204 + uu) * GPU + bp];
                float2 d2n = g2[(255 + uu) * GPU + bp];
                float2 hold = *(const float2*)(h2c + hx);
                float r0 = sigf(dir.x + d2r.x), r1 = sigf(dir.y + d2r.y);
                float z0 = sigf(diz.x + d2z.x), z1 = sigf(diz.y + d2z.y);
                float n0 = tanh_f(fmaf(r0, d2n.x, din.x));
                float n1 = tanh_f(fmaf(r1, d2n.y, din.y));
                float h0 = n0 + z0 * (hold.x - n0);
                float h1 = n1 + z1 * (hold.y - n1);
                *(float2*)(h2n + hx) = make_float2(h0, h1);
                float wl = tabs[6 * H + uu];
                atomicAdd(&oa[2 * bp],     wl * h0);
                atomicAdd(&oa[2 * bp + 1], wl * h1);
            }
            __syncthreads();
            if (tid < BB)
                out[(size_t)(gb0 + tid) * TOT + (i - 1)] = oa[tid] + blin;
            for (int j = tid; j < 408; j += NTHREADS) {
                int uu = j >> 3, bp = j & 7;
                int hx = hidx(uu) + 2 * bp;
                float2 x2 = *(const float2*)(oa + 2 * bp);
                x2.x += blin; x2.y += blin;
                float2 ar = g2[uu * GPU + bp];
                float2 az = g2[(51 + uu) * GPU + bp];
                float2 an = g2[(102 + uu) * GPU + bp];
                float2 hold = *(const float2*)(h1c + hx);
                float w1r = tabs[uu], w1z = tabs[H + uu], w1n = tabs[2 * H + uu];
                float c1r = tabs[3 * H + uu], c1z = tabs[4 * H + uu], c1n = tabs[5 * H + uu];
                float r0 = sigf(fmaf(x2.x, w1r, c1r) + ar.x);
                float r1 = sigf(fmaf(x2.y, w1r, c1r) + ar.y);
                float z0 = sigf(fmaf(x2.x, w1z, c1z) + az.x);
                float z1 = sigf(fmaf(x2.y, w1z, c1z) + az.y);
                float n0 = tanh_f(fmaf(x2.x, w1n, c1n) + r0 * an.x);
                float n1 = tanh_f(fmaf(x2.y, w1n, c1n) + r1 * an.y);
                float h0 = n0 + z0 * (hold.x - n0);
                float h1 = n1 + z1 * (hold.y - n1);
                *(float2*)(h1n + hx) = make_float2(h0, h1);
            }
            __syncthreads();
        }
    }
}

extern "C" void kernel_launch(void* const* d_in, const int* in_sizes, int n_in,
                              void* d_out, int out_size) {
    const float* input = (const float*)d_in[0];
    const float* w_ih1 = (const float*)d_in[2];
    const float* w_hh1 = (const float*)d_in[3];
    const float* b_ih1 = (const float*)d_in[4];
    const float* b_hh1 = (const float*)d_in[5];
    const float* w_ih2 = (const float*)d_in[6];
    const float* w_hh2 = (const float*)d_in[7];
    const float* b_ih2 = (const float*)d_in[8];
    const float* b_hh2 = (const float*)d_in[9];
    const float* w_lin = (const float*)d_in[10];
    const float* b_lin = (const float*)d_in[11];

    const int B   = 2048;
    const int T   = in_sizes[0] / B;
    const int TOT = out_size / B;
    const int F   = TOT - T;

    size_t smem = (size_t)(HT2 + 2 * HSTRIDE + GROWS * GPF + 7 * H + 1 + BB + 2 * BB + 2 * REDS) * sizeof(float);
    cudaFuncSetAttribute(gru2_kernel, cudaFuncAttributeMaxDynamicSharedMemorySize, (int)smem);

    gru2_kernel<<<B / BB, NTHREADS, smem>>>(
        input, w_ih1, w_hh1, b_ih1, b_hh1,
        w_ih2, w_hh2, b_ih2, b_hh2,
        w_lin, b_lin, (float*)d_out, T, F);
}

// round 14
// speedup vs baseline: 1.0017x; 1.0017x over previous
#include <cuda_runtime.h>

#define H 51
#define NTHREADS 576
#define KHALF 26
#define HS 416            // h stride per parity (floats) = 52*8, 1664B ≡ 0 mod 128
#define H2OFF 840         // h2 offset in group block: 3360B ≡ 32 mod 128
#define GBLK 1696         // per-group h block (floats): 6784B ≡ 0 mod 128
#define GROWS 462         // 3 regions x 154
#define GPITCH 5          // gbuf pitch (ull / float2)
#define REDR 9            // reduction rows (3 warps x 3 passes)

typedef unsigned long long ull;

#define FFMA2(d, a, b_) asm("fma.rn.f32x2 %0, %1, %2, %0;" : "+l"(d) : "l"(a), "l"(b_))
#define ADDF2(d, a)     asm("add.rn.f32x2 %0, %0, %1;"     : "+l"(d) : "l"(a))

__device__ __forceinline__ ull pack2(float lo, float hi) {
    ull r;
    asm("mov.b64 %0, {%1,%2};" : "=l"(r) : "f"(lo), "f"(hi));
    return r;
}
__device__ __forceinline__ float2 unpack2(ull v) {
    float lo, hi;
    asm("mov.b64 {%0,%1}, %2;" : "=f"(lo), "=f"(hi) : "l"(v));
    return make_float2(lo, hi);
}
__device__ __forceinline__ float sigf(float v)   { return __fdividef(1.0f, 1.0f + __expf(-v)); }
__device__ __forceinline__ float tanh_f(float v) { return 1.0f - __fdividef(2.0f, __expf(2.0f * v) + 1.0f); }

__global__ __launch_bounds__(NTHREADS, 1)
void gru2_kernel(const float* __restrict__ input,
                 const float* __restrict__ w_ih1, const float* __restrict__ w_hh1,
                 const float* __restrict__ b_ih1, const float* __restrict__ b_hh1,
                 const float* __restrict__ w_ih2, const float* __restrict__ w_hh2,
                 const float* __restrict__ b_ih2, const float* __restrict__ b_hh2,
                 const float* __restrict__ w_lin, const float* __restrict__ b_lin,
                 float* __restrict__ out, int T, int F)
{
    extern __shared__ float sm[];
    float* hbuf = sm;                                  // [2 groups][GBLK]
    ull*   gU   = (ull*)(sm + 2 * GBLK);               // [2*462][5]
    float2* g2  = (float2*)gU;
    float* tabs = sm + 2 * GBLK + 2 * GROWS * 2 * GPITCH;  // 358 floats
    float* xbuf = tabs + 358;                          // [2][8]
    float* oacc = xbuf + 16;                           // [2][2][8]
    float* red  = oacc + 32;                           // [2][2][9][8]

    const int tid  = threadIdx.x;
    const int lane = tid & 31;
    const int gb0  = blockIdx.x * 16;
    const int TOT  = T + F;

    for (int j = tid; j < 2 * GBLK; j += NTHREADS) sm[j] = 0.f;
    for (int j = tid; j < 32 + 2 * 2 * REDR * 8; j += NTHREADS) oacc[j] = 0.f;
    if (tid < H) {
        tabs[tid]         = __ldg(&w_ih1[tid]);
        tabs[H + tid]     = __ldg(&w_ih1[H + tid]);
        tabs[2 * H + tid] = __ldg(&w_ih1[2 * H + tid]);
        tabs[3 * H + tid] = __ldg(&b_ih1[tid]);
        tabs[4 * H + tid] = __ldg(&b_ih1[H + tid]);
        tabs[5 * H + tid] = __ldg(&b_ih1[2 * H + tid]);
        tabs[6 * H + tid] = __ldg(&w_lin[tid]);
    }

    // ---- dot engines: threads 0..461 (warps 0..14), row-pairs x k-split ----
    const bool comp = (tid < 462);
    const int p    = tid >> 1;
    const int half = tid & 1;
    const unsigned pmask = 0x3u << (tid & 30);
    const int region = comp ? (p / 77) : 0;
    const int q  = p - region * 77;
    const int ra = 2 * q, rb = 2 * q + 1;
    const bool vB = (rb < 153);
    const float* wsrc = (region == 0) ? w_hh1 : ((region == 1) ? w_hh2 : w_ih2);
    const float* bsrc = (region == 0) ? b_hh1 : ((region == 1) ? b_hh2 : b_ih2);
    const int hsel = (region == 1);

    float wA[KHALF], wB[KHALF];
    #pragma unroll
    for (int j = 0; j < KHALF; ++j) {
        int k = half * KHALF + j;
        wA[j] = (comp && k < H) ? __ldg(&wsrc[ra * H + k]) : 0.f;
        wB[j] = (comp && vB && k < H) ? __ldg(&wsrc[rb * H + k]) : 0.f;
    }
    float bA  = comp ? __ldg(&bsrc[ra]) : 0.f;
    float bBv = (comp && vB) ? __ldg(&bsrc[rb]) : 0.f;
    const ull biasA = half ? 0ULL : pack2(bA, bA);
    const ull biasB = half ? 0ULL : pack2(bBv, bBv);
    const float blin = __ldg(&b_lin[0]);
    const int pxor   = hsel ? 0 : 1;
    const int clsOff = (hsel ? H2OFF : 0) + half * (KHALF * 8);  // half-1 at 832B ≡ 64
    const int growA  = region * 154 + ra;

    const int pwt = tid - 480;   // pw engines: threads 480..575 (warps 15..17)

    __syncthreads();

    const int PHEND = 2 * TOT + 2;
    for (int ph = 0; ph <= PHEND; ++ph) {
        const int gd = ph & 1;        // dot group
        const int id = ph >> 1;       // dot step
        const int gp = gd ^ 1;        // pw group
        const int ip = (ph - 1) >> 1; // pw step

        // ================= DOT (group gd, step id) =================
        if (comp) {
            if (id <= TOT) {
                const int par = id & 1;
                const float* hp = hbuf + gd * GBLK + clsOff + (par ^ pxor) * HS;
                ull aA0 = biasA, aA1 = biasA, aA2 = biasA, aA3 = biasA;
                ull aB0 = biasB, aB1 = biasB, aB2 = biasB, aB3 = biasB;
                #pragma unroll
                for (int k = 0; k < KHALF; ++k) {
                    const ull wdA = pack2(wA[k], wA[k]);
                    const ull wdB = pack2(wB[k], wB[k]);
                    const ulonglong2* qq = (const ulonglong2*)(hp + k * 8);
                    ulonglong2 q0 = qq[0], q1 = qq[1];
                    FFMA2(aA0, wdA, q0.x); FFMA2(aA1, wdA, q0.y);
                    FFMA2(aA2, wdA, q1.x); FFMA2(aA3, wdA, q1.y);
                    FFMA2(aB0, wdB, q0.x); FFMA2(aB1, wdB, q0.y);
                    FFMA2(aB2, wdB, q1.x); FFMA2(aB3, wdB, q1.y);
                }
                ull t;
                t = __shfl_xor_sync(pmask, aA0, 1); ADDF2(aA0, t);
                t = __shfl_xor_sync(pmask, aA1, 1); ADDF2(aA1, t);
                t = __shfl_xor_sync(pmask, aA2, 1); ADDF2(aA2, t);
                t = __shfl_xor_sync(pmask, aA3, 1); ADDF2(aA3, t);
                t = __shfl_xor_sync(pmask, aB0, 1); ADDF2(aB0, t);
                t = __shfl_xor_sync(pmask, aB1, 1); ADDF2(aB1, t);
                t = __shfl_xor_sync(pmask, aB2, 1); ADDF2(aB2, t);
                t = __shfl_xor_sync(pmask, aB3, 1); ADDF2(aB3, t);
                if (!half) {
                    ull* gA = gU + (gd * GROWS + growA) * GPITCH;
                    gA[0] = aA0; gA[1] = aA1; gA[2] = aA2; gA[3] = aA3;
                    ull* gB = gA + GPITCH;
                    gB[0] = aB0; gB[1] = aB1; gB[2] = aB2; gB[3] = aB3;
                }
            }
        } else if (tid >= 464 && tid < 472) {
            // x prefetch for pw(gd, id) next phase
            if (id < T) xbuf[gd * 8 + (tid - 464)] =
                __ldg(&input[(size_t)(gb0 + gd * 8 + (tid - 464)) * T + id]);
        }

        // ================= POINTWISE (group gp, step ip) =================
        if (pwt >= 0 && ph >= 1 && ip <= TOT) {
            const int par = ip & 1;
            float* hg = hbuf + gp * GBLK;
            const int GB = gp * GROWS;
            if (ip < T) {
                // finalize o[ip-2] from red scratch
                if (ip >= 2 && pwt < 8) {
                    const float* rr = red + (gp * 2 + par) * REDR * 8;
                    float s = 0.f;
                    #pragma unroll
                    for (int r = 0; r < REDR; ++r) s += rr[r * 8 + pwt];
                    out[(size_t)(gb0 + gp * 8 + pwt) * TOT + (ip - 2)] = s + blin;
                }
                // L2 pointwise + shfl reduction -> red[gp][par^1]
                float* h2c = hg + H2OFF + par * HS;
                float* h2n = hg + H2OFF + (par ^ 1) * HS;
                float* rw  = red + (gp * 2 + (par ^ 1)) * REDR * 8 + (pwt >> 5) * 3 * 8;
                #pragma unroll
                for (int pass = 0; pass < 3; ++pass) {
                    int j = pwt + 96 * pass;
                    float v0 = 0.f, v1 = 0.f;
                    if (ip > 0 && j < 204) {
                        int u = j >> 2, bp = j & 3;
                        float2 dir = g2[(GB + 308 + u) * GPITCH + bp];
                        float2 diz = g2[(GB + 359 + u) * GPITCH + bp];
                        float2 din = g2[(GB + 410 + u) * GPITCH + bp];
                        float2 d2r = g2[(GB + 154 + u) * GPITCH + bp];
                        float2 d2z = g2[(GB + 205 + u) * GPITCH + bp];
                        float2 d2n = g2[(GB + 256 + u) * GPITCH + bp];
                        int hx = u * 8 + 2 * bp;
                        float2 hold = *(const float2*)(h2c + hx);
                        float r0 = sigf(dir.x + d2r.x), r1 = sigf(dir.y + d2r.y);
                        float z0 = sigf(diz.x + d2z.x), z1 = sigf(diz.y + d2z.y);
                        float n0 = tanh_f(fmaf(r0, d2n.x, din.x));
                        float n1 = tanh_f(fmaf(r1, d2n.y, din.y));
                        float h0 = n0 + z0 * (hold.x - n0);
                        float h1 = n1 + z1 * (hold.y - n1);
                        *(float2*)(h2n + hx) = make_float2(h0, h1);
                        float wl = tabs[6 * H + u];
                        v0 = wl * h0; v1 = wl * h1;
                    }
                    ull pv = pack2(v0, v1), t;
                    t = __shfl_xor_sync(0xFFFFFFFFu, pv, 4);  ADDF2(pv, t);
                    t = __shfl_xor_sync(0xFFFFFFFFu, pv, 8);  ADDF2(pv, t);
                    t = __shfl_xor_sync(0xFFFFFFFFu, pv, 16); ADDF2(pv, t);
                    if (lane < 4) *(float2*)(rw + pass * 8 + 2 * lane) = unpack2(pv);
                }
                // L1 pointwise
                float* h1c = hg + (par ^ 1) * HS;
                float* h1n = hg + par * HS;
                #pragma unroll
                for (int pass = 0; pass < 3; ++pass) {
                    int j = pwt + 96 * pass;
                    if (j < 204) {
                        int u = j >> 2, bp = j & 3;
                        float2 x2 = *(const float2*)(xbuf + gp * 8 + 2 * bp);
                        float2 ar = g2[(GB + u) * GPITCH + bp];
                        float2 az = g2[(GB + 51 + u) * GPITCH + bp];
                        float2 an = g2[(GB + 102 + u) * GPITCH + bp];
                        int hx = u * 8 + 2 * bp;
                        float2 hold = *(const float2*)(h1c + hx);
                        float w1r = tabs[u], w1z = tabs[H + u], w1n = tabs[2 * H + u];
                        float c1r = tabs[3 * H + u], c1z = tabs[4 * H + u], c1n = tabs[5 * H + u];
                        float r0 = sigf(fmaf(x2.x, w1r, c1r) + ar.x);
                        float r1 = sigf(fmaf(x2.y, w1r, c1r) + ar.y);
                        float z0 = sigf(fmaf(x2.x, w1z, c1z) + az.x);
                        float z1 = sigf(fmaf(x2.y, w1z, c1z) + az.y);
                        float n0 = tanh_f(fmaf(x2.x, w1n, c1n) + r0 * an.x);
                        float n1 = tanh_f(fmaf(x2.y, w1n, c1n) + r1 * an.y);
                        float h0 = n0 + z0 * (hold.x - n0);
                        float h1 = n1 + z1 * (hold.y - n1);
                        *(float2*)(h1n + hx) = make_float2(h0, h1);
                    }
                }
            } else {
                // -------- future mode (o feedback) --------
                float* oa  = oacc + (gp * 2 + par) * 8;
                float* h2c = hg + H2OFF + par * HS;
                float* h2n = hg + H2OFF + (par ^ 1) * HS;
                #pragma unroll
                for (int pass = 0; pass < 3; ++pass) {
                    int j = pwt + 96 * pass;
                    if (j < 204) {
                        int u = j >> 2, bp = j & 3;
                        float2 dir = g2[(GB + 308 + u) * GPITCH + bp];
                        float2 diz = g2[(GB + 359 + u) * GPITCH + bp];
                        float2 din = g2[(GB + 410 + u) * GPITCH + bp];
                        float2 d2r = g2[(GB + 154 + u) * GPITCH + bp];
                        float2 d2z = g2[(GB + 205 + u) * GPITCH + bp];
                        float2 d2n = g2[(GB + 256 + u) * GPITCH + bp];
                        int hx = u * 8 + 2 * bp;
                        float2 hold = *(const float2*)(h2c + hx);
                        float r0 = sigf(dir.x + d2r.x), r1 = sigf(dir.y + d2r.y);
                        float z0 = sigf(diz.x + d2z.x), z1 = sigf(diz.y + d2z.y);
                        float n0 = tanh_f(fmaf(r0, d2n.x, din.x));
                        float n1 = tanh_f(fmaf(r1, d2n.y, din.y));
                        float h0 = n0 + z0 * (hold.x - n0);
                        float h1 = n1 + z1 * (hold.y - n1);
                        *(float2*)(h2n + hx) = make_float2(h0, h1);
                        float wl = tabs[6 * H + u];
                        atomicAdd(&oa[2 * bp],     wl * h0);
                        atomicAdd(&oa[2 * bp + 1], wl * h1);
                    }
                }
                if (ip == T && pwt < 8) {   // flush the last red-based output o[T-2]
                    const float* rr = red + (gp * 2 + par) * REDR * 8;
                    float s = 0.f;
                    #pragma unroll
                    for (int r = 0; r < REDR; ++r) s += rr[r * 8 + pwt];
                    out[(size_t)(gb0 + gp * 8 + pwt) * TOT + (T - 2)] = s + blin;
                }
                asm volatile("bar.sync 1, 96;" ::: "memory");
                if (pwt < 8) {
                    out[(size_t)(gb0 + gp * 8 + pwt) * TOT + (ip - 1)] = oa[pwt] + blin;
                    oacc[(gp * 2 + (par ^ 1)) * 8 + pwt] = 0.f;
                }
                if (ip < TOT) {
                    float* h1c = hg + (par ^ 1) * HS;
                    float* h1n = hg + par * HS;
                    #pragma unroll
                    for (int pass = 0; pass < 3; ++pass) {
                        int j = pwt + 96 * pass;
                        if (j < 204) {
                            int u = j >> 2, bp = j & 3;
                            float2 x2 = *(const float2*)(oa + 2 * bp);
                            x2.x += blin; x2.y += blin;
                            float2 ar = g2[(GB + u) * GPITCH + bp];
                            float2 az = g2[(GB + 51 + u) * GPITCH + bp];
                            float2 an = g2[(GB + 102 + u) * GPITCH + bp];
                            int hx = u * 8 + 2 * bp;
                            float2 hold = *(const float2*)(h1c + hx);
                            float w1r = tabs[u], w1z = tabs[H + u], w1n = tabs[2 * H + u];
                            float c1r = tabs[3 * H + u], c1z = tabs[4 * H + u], c1n = tabs[5 * H + u];
                            float r0 = sigf(fmaf(x2.x, w1r, c1r) + ar.x);
                            float r1 = sigf(fmaf(x2.y, w1r, c1r) + ar.y);
                            float z0 = sigf(fmaf(x2.x, w1z, c1z) + az.x);
                            float z1 = sigf(fmaf(x2.y, w1z, c1z) + az.y);
                            float n0 = tanh_f(fmaf(x2.x, w1n, c1n) + r0 * an.x);
                            float n1 = tanh_f(fmaf(x2.y, w1n, c1n) + r1 * an.y);
                            float h0 = n0 + z0 * (hold.x - n0);
                            float h1 = n1 + z1 * (hold.y - n1);
                            *(float2*)(h1n + hx) = make_float2(h0, h1);
                        }
                    }
                }
            }
        }
        __syncthreads();
    }
}

extern "C" void kernel_launch(void* const* d_in, const int* in_sizes, int n_in,
                              void* d_out, int out_size) {
    const float* input = (const float*)d_in[0];
    const float* w_ih1 = (const float*)d_in[2];
    const float* w_hh1 = (const float*)d_in[3];
    const float* b_ih1 = (const float*)d_in[4];
    const float* b_hh1 = (const float*)d_in[5];
    const float* w_ih2 = (const float*)d_in[6];
    const float* w_hh2 = (const float*)d_in[7];
    const float* b_ih2 = (const float*)d_in[8];
    const float* b_hh2 = (const float*)d_in[9];
    const float* w_lin = (const float*)d_in[10];
    const float* b_lin = (const float*)d_in[11];

    const int B   = 2048;
    const int T   = in_sizes[0] / B;
    const int TOT = out_size / B;
    const int F   = TOT - T;

    size_t smem = (size_t)(2 * GBLK + 2 * GROWS * 2 * GPITCH + 358 + 16 + 32 + 2 * 2 * REDR * 8) * sizeof(float);
    cudaFuncSetAttribute(gru2_kernel, cudaFuncAttributeMaxDynamicSharedMemorySize, (int)smem);

    gru2_kernel<<<B / 16, NTHREADS, smem>>>(
        input, w_ih1, w_hh1, b_ih1, b_hh1,
        w_ih2, w_hh2, b_ih2, b_hh2,
        w_lin, b_lin, (float*)d_out, T, F);
}

// round 15
// speedup vs baseline: 1.1125x; 1.1106x over previous
#include <cuda_runtime.h>

#define H 51
#define BB 16
#define NTHREADS 512
#define KHALF 26         // k's per half (pad 51 -> 52)
#define HOFF 424         // half-1 k-range float offset (1696B ≡ 32 mod 128)
#define HSTRIDE 840      // floats per h buffer: 52*16 + 8 gap
#define GROWS 462        // gbuf rows: 3 regions x 154
#define GPUP 10          // gbuf pitch (ull) = 80B, 16B-aligned
#define GR2 154
#define GR3 308
#define OFF_TABS 12600   // float offsets in smem
#define OFF_XBUF 12960
#define OFF_OACC 12976
#define OFF_RED  13008   // [2][7][16]
#define SMEM_FLOATS 13232

typedef unsigned long long ull;

#define FFMA2(d, a, b_) asm("fma.rn.f32x2 %0, %1, %2, %0;" : "+l"(d) : "l"(a), "l"(b_))
#define ADDF2(d, a)     asm("add.rn.f32x2 %0, %0, %1;"     : "+l"(d) : "l"(a))

__device__ __forceinline__ ull pack2(float lo, float hi) {
    ull r;
    asm("mov.b64 %0, {%1,%2};" : "=l"(r) : "f"(lo), "f"(hi));
    return r;
}
__device__ __forceinline__ float2 unpack2(ull v) {
    float lo, hi;
    asm("mov.b64 {%0,%1}, %2;" : "=f"(lo), "=f"(hi) : "l"(v));
    return make_float2(lo, hi);
}
__device__ __forceinline__ float sigf(float v)   { return __fdividef(1.0f, 1.0f + __expf(-v)); }
__device__ __forceinline__ float tanh_f(float v) { return 1.0f - __fdividef(2.0f, __expf(2.0f * v) + 1.0f); }
__device__ __forceinline__ int hidx(int k) { return k * 16 + (k >= KHALF ? 8 : 0); }

__global__ __launch_bounds__(NTHREADS, 1)
void gru2_kernel(const float* __restrict__ input,
                 const float* __restrict__ w_ih1, const float* __restrict__ w_hh1,
                 const float* __restrict__ b_ih1, const float* __restrict__ b_hh1,
                 const float* __restrict__ w_ih2, const float* __restrict__ w_hh2,
                 const float* __restrict__ b_ih2, const float* __restrict__ b_hh2,
                 const float* __restrict__ w_lin, const float* __restrict__ b_lin,
                 float* __restrict__ out, int T, int F)
{
    extern __shared__ float sm[];
    float* hT1   = sm;                          // [2][840]
    float* hT2   = sm + 2 * HSTRIDE;            // [2][840]  (byte 6720 ≡ 64 mod 128)
    ull*   gbufU = (ull*)(sm + 4 * HSTRIDE);    // [462][10]
    const float4* g4 = (const float4*)gbufU;    // row pitch = 5 float4
    float* tabs  = sm + OFF_TABS;               // 7*51 used
    float* xbuf  = sm + OFF_XBUF;               // [16]
    float* oacc  = sm + OFF_OACC;               // [2][16]
    float* red   = sm + OFF_RED;                // [2][7][16]

    const int tid  = threadIdx.x;
    const int lane = tid & 31;
    const int gb0  = blockIdx.x * BB;
    const int TOT  = T + F;

    for (int j = tid; j < 4 * HSTRIDE; j += NTHREADS) sm[j] = 0.f;
    for (int j = tid; j < 256; j += NTHREADS) oacc[j] = 0.f;   // oacc + red contiguous
    if (tid < H) {
        tabs[tid]         = __ldg(&w_ih1[tid]);
        tabs[H + tid]     = __ldg(&w_ih1[H + tid]);
        tabs[2 * H + tid] = __ldg(&w_ih1[2 * H + tid]);
        tabs[3 * H + tid] = __ldg(&b_ih1[tid]);
        tabs[4 * H + tid] = __ldg(&b_ih1[H + tid]);
        tabs[5 * H + tid] = __ldg(&b_ih1[2 * H + tid]);
        tabs[6 * H + tid] = __ldg(&w_lin[tid]);
    }

    // ---- dot setup (R12 core: 231 row-pairs x k-split-2) ----
    const bool comp = (tid < 462);
    const int P    = comp ? (tid >> 1) : 0;
    const int half = tid & 1;
    const unsigned pmask = 0x3u << (tid & 30);
    const int region = P / 77;
    const int q      = P - region * 77;
    const int ra = 2 * q, rb = 2 * q + 1;
    const bool vB = (rb < 153);
    const float* wsrc = (region == 0) ? w_hh1 : ((region == 1) ? w_hh2 : w_ih2);
    const float* bsrc = (region == 0) ? b_hh1 : ((region == 1) ? b_hh2 : b_ih2);
    const int hsel = (region == 1);

    float wA[KHALF], wB[KHALF];
    #pragma unroll
    for (int j = 0; j < KHALF; ++j) {
        int k = half * KHALF + j;
        wA[j] = (comp && k < H) ? __ldg(&wsrc[ra * H + k]) : 0.f;
        wB[j] = (comp && vB && k < H) ? __ldg(&wsrc[rb * H + k]) : 0.f;
    }
    float bA  = comp ? __ldg(&bsrc[ra]) : 0.f;
    float bBv = (comp && vB) ? __ldg(&bsrc[rb]) : 0.f;
    const ull biasA = half ? 0ULL : pack2(bA, bA);
    const ull biasB = half ? 0ULL : pack2(bBv, bBv);
    const float blin = __ldg(&b_lin[0]);
    const int pxor = hsel ? 0 : 1;
    const float* hbase = hsel ? hT2 : hT1;
    const int hoff = half * HOFF;
    const int growA = region * 154 + ra;

    __syncthreads();

    for (int i = 0; i <= TOT; ++i) {
        const int par = i & 1;

        // ================= DOT STAGE (R12 core) + helper warp 15 =================
        if (comp) {
            const float* hp = hbase + (par ^ pxor) * HSTRIDE + hoff;
            ull aA[8], aB[8];
            #pragma unroll
            for (int bp = 0; bp < 8; ++bp) { aA[bp] = biasA; aB[bp] = biasB; }
            #pragma unroll
            for (int k = 0; k < KHALF; ++k) {
                const ull wdA = pack2(wA[k], wA[k]);
                const ull wdB = pack2(wB[k], wB[k]);
                const ulonglong2* qq = (const ulonglong2*)(hp + k * 16);
                ulonglong2 q0 = qq[0], q1 = qq[1], q2 = qq[2], q3 = qq[3];
                FFMA2(aA[0], wdA, q0.x); FFMA2(aA[1], wdA, q0.y);
                FFMA2(aA[2], wdA, q1.x); FFMA2(aA[3], wdA, q1.y);
                FFMA2(aA[4], wdA, q2.x); FFMA2(aA[5], wdA, q2.y);
                FFMA2(aA[6], wdA, q3.x); FFMA2(aA[7], wdA, q3.y);
                FFMA2(aB[0], wdB, q0.x); FFMA2(aB[1], wdB, q0.y);
                FFMA2(aB[2], wdB, q1.x); FFMA2(aB[3], wdB, q1.y);
                FFMA2(aB[4], wdB, q2.x); FFMA2(aB[5], wdB, q2.y);
                FFMA2(aB[6], wdB, q3.x); FFMA2(aB[7], wdB, q3.y);
            }
            #pragma unroll
            for (int bp = 0; bp < 8; ++bp) {
                ull t;
                t = __shfl_xor_sync(pmask, aA[bp], 1); ADDF2(aA[bp], t);
                t = __shfl_xor_sync(pmask, aB[bp], 1); ADDF2(aB[bp], t);
            }
            if (!half) {
                ulonglong2* gA = (ulonglong2*)(gbufU + growA * GPUP);
                ulonglong2* gB = (ulonglong2*)(gbufU + (growA + 1) * GPUP);
                gA[0] = make_ulonglong2(aA[0], aA[1]);
                gA[1] = make_ulonglong2(aA[2], aA[3]);
                gA[2] = make_ulonglong2(aA[4], aA[5]);
                gA[3] = make_ulonglong2(aA[6], aA[7]);
                gB[0] = make_ulonglong2(aB[0], aB[1]);
                gB[1] = make_ulonglong2(aB[2], aB[3]);
                gB[2] = make_ulonglong2(aB[4], aB[5]);
                gB[3] = make_ulonglong2(aB[6], aB[7]);
            }
        } else if (tid >= 480) {
            int l = tid - 480;
            if (l < 16) {
                if (i >= 2 && i <= T) {           // finalize o[i-2]
                    const float* rr = red + (par ^ 1) * 112;
                    float s = rr[l] + rr[16 + l] + rr[32 + l] + rr[48 + l]
                            + rr[64 + l] + rr[80 + l] + rr[96 + l];
                    out[(size_t)(gb0 + l) * TOT + (i - 2)] = s + blin;
                }
                if (i >= T) oacc[par * 16 + l] = 0.f;
                if (i < T)  xbuf[l] = __ldg(&input[(size_t)(gb0 + l) * T + i]);
            }
        }
        __syncthreads();

        // ================= POINTWISE STAGE =================
        float* h2c = hT2 + par * HSTRIDE;          // h2[i-2]
        float* h2n = hT2 + (par ^ 1) * HSTRIDE;    // h2[i-1]
        float* h1c = hT1 + (par ^ 1) * HSTRIDE;    // h1[i-1]
        float* h1n = hT1 + par * HSTRIDE;          // h1[i]

        if (i < T) {
            // ---- L2 pointwise + shfl-tree reduction: warps 0-6 (float4 tasks) ----
            if (tid < 224) {
                int u = tid >> 2, bp = tid & 3;
                int uc = (u < H) ? u : 0;
                bool act = (i > 0) && (u < H);
                float4 v = make_float4(0.f, 0.f, 0.f, 0.f);
                if (act) {
                    float4 dir = g4[(GR3 + uc) * 5 + bp];
                    float4 diz = g4[(GR3 + 51 + uc) * 5 + bp];
                    float4 din = g4[(GR3 + 102 + uc) * 5 + bp];
                    float4 d2r = g4[(GR2 + uc) * 5 + bp];
                    float4 d2z = g4[(GR2 + 51 + uc) * 5 + bp];
                    float4 d2n = g4[(GR2 + 102 + uc) * 5 + bp];
                    int hx = hidx(uc) + 4 * bp;
                    float4 hold = *(const float4*)(h2c + hx);
                    float r0 = sigf(dir.x + d2r.x), r1 = sigf(dir.y + d2r.y);
                    float r2 = sigf(dir.z + d2r.z), r3 = sigf(dir.w + d2r.w);
                    float z0 = sigf(diz.x + d2z.x), z1 = sigf(diz.y + d2z.y);
                    float z2 = sigf(diz.z + d2z.z), z3 = sigf(diz.w + d2z.w);
                    float n0 = tanh_f(fmaf(r0, d2n.x, din.x));
                    float n1 = tanh_f(fmaf(r1, d2n.y, din.y));
                    float n2 = tanh_f(fmaf(r2, d2n.z, din.z));
                    float n3 = tanh_f(fmaf(r3, d2n.w, din.w));
                    float h0 = n0 + z0 * (hold.x - n0);
                    float h1 = n1 + z1 * (hold.y - n1);
                    float h2 = n2 + z2 * (hold.z - n2);
                    float h3 = n3 + z3 * (hold.w - n3);
                    *(float4*)(h2n + hx) = make_float4(h0, h1, h2, h3);
                    float wl = tabs[6 * H + uc];
                    v = make_float4(wl * h0, wl * h1, wl * h2, wl * h3);
                }
                ull p01 = pack2(v.x, v.y), p23 = pack2(v.z, v.w), t;
                t = __shfl_xor_sync(0xFFFFFFFFu, p01, 4);  ADDF2(p01, t);
                t = __shfl_xor_sync(0xFFFFFFFFu, p23, 4);  ADDF2(p23, t);
                t = __shfl_xor_sync(0xFFFFFFFFu, p01, 8);  ADDF2(p01, t);
                t = __shfl_xor_sync(0xFFFFFFFFu, p23, 8);  ADDF2(p23, t);
                t = __shfl_xor_sync(0xFFFFFFFFu, p01, 16); ADDF2(p01, t);
                t = __shfl_xor_sync(0xFFFFFFFFu, p23, 16); ADDF2(p23, t);
                if (lane < 4) {
                    float2 a2 = unpack2(p01), b2 = unpack2(p23);
                    *(float4*)(red + par * 112 + (tid >> 5) * 16 + 4 * lane)
                        = make_float4(a2.x, a2.y, b2.x, b2.y);
                }
            } else if (tid >= 256 && tid < 464) {
                // ---- L1 pointwise: warps 8-14 (float4 tasks) ----
                int j2 = tid - 256;
                int u = j2 >> 2, bp = j2 & 3;
                if (u < H) {
                    float4 x4 = *(const float4*)(xbuf + 4 * bp);
                    float4 ar = g4[u * 5 + bp];
                    float4 az = g4[(51 + u) * 5 + bp];
                    float4 an = g4[(102 + u) * 5 + bp];
                    int hx = hidx(u) + 4 * bp;
                    float4 hold = *(const float4*)(h1c + hx);
                    float w1r = tabs[u], w1z = tabs[H + u], w1n = tabs[2 * H + u];
                    float c1r = tabs[3 * H + u], c1z = tabs[4 * H + u], c1n = tabs[5 * H + u];
                    float r0 = sigf(fmaf(x4.x, w1r, c1r) + ar.x);
                    float r1 = sigf(fmaf(x4.y, w1r, c1r) + ar.y);
                    float r2 = sigf(fmaf(x4.z, w1r, c1r) + ar.z);
                    float r3 = sigf(fmaf(x4.w, w1r, c1r) + ar.w);
                    float z0 = sigf(fmaf(x4.x, w1z, c1z) + az.x);
                    float z1 = sigf(fmaf(x4.y, w1z, c1z) + az.y);
                    float z2 = sigf(fmaf(x4.z, w1z, c1z) + az.z);
                    float z3 = sigf(fmaf(x4.w, w1z, c1z) + az.w);
                    float n0 = tanh_f(fmaf(x4.x, w1n, c1n) + r0 * an.x);
                    float n1 = tanh_f(fmaf(x4.y, w1n, c1n) + r1 * an.y);
                    float n2 = tanh_f(fmaf(x4.z, w1n, c1n) + r2 * an.z);
                    float n3 = tanh_f(fmaf(x4.w, w1n, c1n) + r3 * an.w);
                    float h0 = n0 + z0 * (hold.x - n0);
                    float h1 = n1 + z1 * (hold.y - n1);
                    float h2 = n2 + z2 * (hold.z - n2);
                    float h3 = n3 + z3 * (hold.w - n3);
                    *(float4*)(h1n + hx) = make_float4(h0, h1, h2, h3);
                }
            }
            __syncthreads();
        } else {
            // ---- future mode: L2 (+atomic o) -> sync -> out + L1 -> sync ----
            float* oa = oacc + par * 16;
            if (tid < 224) {
                int u = tid >> 2, bp = tid & 3;
                if (u < H) {
                    float4 dir = g4[(GR3 + u) * 5 + bp];
                    float4 diz = g4[(GR3 + 51 + u) * 5 + bp];
                    float4 din = g4[(GR3 + 102 + u) * 5 + bp];
                    float4 d2r = g4[(GR2 + u) * 5 + bp];
                    float4 d2z = g4[(GR2 + 51 + u) * 5 + bp];
                    float4 d2n = g4[(GR2 + 102 + u) * 5 + bp];
                    int hx = hidx(u) + 4 * bp;
                    float4 hold = *(const float4*)(h2c + hx);
                    float r0 = sigf(dir.x + d2r.x), r1 = sigf(dir.y + d2r.y);
                    float r2 = sigf(dir.z + d2r.z), r3 = sigf(dir.w + d2r.w);
                    float z0 = sigf(diz.x + d2z.x), z1 = sigf(diz.y + d2z.y);
                    float z2 = sigf(diz.z + d2z.z), z3 = sigf(diz.w + d2z.w);
                    float n0 = tanh_f(fmaf(r0, d2n.x, din.x));
                    float n1 = tanh_f(fmaf(r1, d2n.y, din.y));
                    float n2 = tanh_f(fmaf(r2, d2n.z, din.z));
                    float n3 = tanh_f(fmaf(r3, d2n.w, din.w));
                    float h0 = n0 + z0 * (hold.x - n0);
                    float h1 = n1 + z1 * (hold.y - n1);
                    float h2 = n2 + z2 * (hold.z - n2);
                    float h3 = n3 + z3 * (hold.w - n3);
                    *(float4*)(h2n + hx) = make_float4(h0, h1, h2, h3);
                    float wl = tabs[6 * H + u];
                    atomicAdd(&oa[4 * bp],     wl * h0);
                    atomicAdd(&oa[4 * bp + 1], wl * h1);
                    atomicAdd(&oa[4 * bp + 2], wl * h2);
                    atomicAdd(&oa[4 * bp + 3], wl * h3);
                }
            }
            __syncthreads();
            if (tid < BB)
                out[(size_t)(gb0 + tid) * TOT + (i - 1)] = oa[tid] + blin;
            if (tid >= 256 && tid < 464) {
                int j2 = tid - 256;
                int u = j2 >> 2, bp = j2 & 3;
                if (u < H) {
                    float4 x4 = *(const float4*)(oa + 4 * bp);
                    x4.x += blin; x4.y += blin; x4.z += blin; x4.w += blin;
                    float4 ar = g4[u * 5 + bp];
                    float4 az = g4[(51 + u) * 5 + bp];
                    float4 an = g4[(102 + u) * 5 + bp];
                    int hx = hidx(u) + 4 * bp;
                    float4 hold = *(const float4*)(h1c + hx);
                    float w1r = tabs[u], w1z = tabs[H + u], w1n = tabs[2 * H + u];
                    float c1r = tabs[3 * H + u], c1z = tabs[4 * H + u], c1n = tabs[5 * H + u];
                    float r0 = sigf(fmaf(x4.x, w1r, c1r) + ar.x);
                    float r1 = sigf(fmaf(x4.y, w1r, c1r) + ar.y);
                    float r2 = sigf(fmaf(x4.z, w1r, c1r) + ar.z);
                    float r3 = sigf(fmaf(x4.w, w1r, c1r) + ar.w);
                    float z0 = sigf(fmaf(x4.x, w1z, c1z) + az.x);
                    float z1 = sigf(fmaf(x4.y, w1z, c1z) + az.y);
                    float z2 = sigf(fmaf(x4.z, w1z, c1z) + az.z);
                    float z3 = sigf(fmaf(x4.w, w1z, c1z) + az.w);
                    float n0 = tanh_f(fmaf(x4.x, w1n, c1n) + r0 * an.x);
                    float n1 = tanh_f(fmaf(x4.y, w1n, c1n) + r1 * an.y);
                    float n2 = tanh_f(fmaf(x4.z, w1n, c1n) + r2 * an.z);
                    float n3 = tanh_f(fmaf(x4.w, w1n, c1n) + r3 * an.w);
                    float h0 = n0 + z0 * (hold.x - n0);
                    float h1 = n1 + z1 * (hold.y - n1);
                    float h2 = n2 + z2 * (hold.z - n2);
                    float h3 = n3 + z3 * (hold.w - n3);
                    *(float4*)(h1n + hx) = make_float4(h0, h1, h2, h3);
                }
            }
            __syncthreads();
        }
    }
}

extern "C" void kernel_launch(void* const* d_in, const int* in_sizes, int n_in,
                              void* d_out, int out_size) {
    const float* input = (const float*)d_in[0];
    const float* w_ih1 = (const float*)d_in[2];
    const float* w_hh1 = (const float*)d_in[3];
    const float* b_ih1 = (const float*)d_in[4];
    const float* b_hh1 = (const float*)d_in[5];
    const float* w_ih2 = (const float*)d_in[6];
    const float* w_hh2 = (const float*)d_in[7];
    const float* b_ih2 = (const float*)d_in[8];
    const float* b_hh2 = (const float*)d_in[9];
    const float* w_lin = (const float*)d_in[10];
    const float* b_lin = (const float*)d_in[11];

    const int B   = 2048;
    const int T   = in_sizes[0] / B;
    const int TOT = out_size / B;
    const int F   = TOT - T;

    size_t smem = (size_t)SMEM_FLOATS * sizeof(float);
    cudaFuncSetAttribute(gru2_kernel, cudaFuncAttributeMaxDynamicSharedMemorySize, (int)smem);

    gru2_kernel<<<B / BB, NTHREADS, smem>>>(
        input, w_ih1, w_hh1, b_ih1, b_hh1,
        w_ih2, w_hh2, b_ih2, b_hh2,
        w_lin, b_lin, (float*)d_out, T, F);
}